// round 4
// baseline (speedup 1.0000x reference)
#include <cuda_runtime.h>
#include <cuda_bf16.h>

#define BATCH 4
#define HW    65536           // 256*256 pixels per (batch,channel)
#define KBINS 512             // 8^3 bins
#define GX    74              // blocks/batch -> 296 CTAs = exactly 2/SM
#define NTHR  1024            // 2 CTAs/SM * 1024 = 2048 thr/SM = 100% occ
// -1 / (49 * 2*sigma^2), sigma = 0.02
#define NEG_COEF (-25.510204081632653f)
// tail truncation: far-bin relative weight at f=0.32 is exp(-25.51*0.36)=1.0e-4
#define TLO 0.32f
#define THI 0.68f

// Scratch (no cudaMalloc). Zero at module load; last block per batch resets
// it each run, preserving the invariant across graph replays.
__device__ float        g_hist[BATCH * KBINS];
__device__ unsigned int g_count[BATCH];

__global__ __launch_bounds__(NTHR, 2)
void dh_fused_kernel(const float* __restrict__ x, float* __restrict__ out) {
    __shared__ float red[32];
    __shared__ int   s_last;

    const int b   = blockIdx.y;
    const int tid = threadIdx.x;

    // per-block contiguous scalar-pixel range: 885 or 886 per block (<=1024)
    const float* __restrict__ xb = x + (size_t)b * 3 * HW;
    const int start = (int)(((long long)blockIdx.x       * HW) / GX);
    const int end   = (int)(((long long)(blockIdx.x + 1) * HW) / GX);
    const int p     = start + tid;

    float* __restrict__ hb = &g_hist[b * KBINS];

    if (p < end) {
        const float tx = __ldg(xb + p)          * 7.0f;
        const float ty = __ldg(xb + HW + p)     * 7.0f;
        const float tz = __ldg(xb + 2 * HW + p) * 7.0f;
        const int ix = min((int)tx, 6);
        const int iy = min((int)ty, 6);
        const int iz = min((int)tz, 6);
        const float fx = tx - (float)ix;
        const float fy = ty - (float)iy;
        const float fz = tz - (float)iz;
        const float gx = 1.0f - fx, gy = 1.0f - fy, gz = 1.0f - fz;

        const float wx0 = __expf(NEG_COEF * fx * fx);
        const float wx1 = __expf(NEG_COEF * gx * gx);
        const float wy0 = __expf(NEG_COEF * fy * fy);
        const float wy1 = __expf(NEG_COEF * gy * gy);
        float       wz0 = __expf(NEG_COEF * fz * fz);
        float       wz1 = __expf(NEG_COEF * gz * gz);

        // exact per-pixel normalizer (all 6 weights; +1e-8 matters)
        const float S   = (wx0 + wx1) * (wy0 + wy1) * (wz0 + wz1);
        const float inv = __fdividef(1.0f, S + 1e-8f);
        wz0 *= inv;
        wz1 *= inv;

        const bool px0 = fx < THI, px1 = fx > TLO;
        const bool py0 = fy < THI, py1 = fy > TLO;
        const bool pz0 = fz < THI, pz1 = fz > TLO;

        const float wyz00 = wy0 * wz0, wyz01 = wy0 * wz1;
        const float wyz10 = wy1 * wz0, wyz11 = wy1 * wz1;
        const int base = ix * 64 + iy * 8 + iz;

        // global no-return atomics -> RED.E.ADD.F32 (0.85-1.3 cyc/lane vs
        // ATOMS 2 cyc/lane); L2 atom ALU pipelines same-address adds ~1/cyc
        if (px0 && py0 && pz0) atomicAdd(hb + base +  0, wx0 * wyz00);
        if (px0 && py0 && pz1) atomicAdd(hb + base +  1, wx0 * wyz01);
        if (px0 && py1 && pz0) atomicAdd(hb + base +  8, wx0 * wyz10);
        if (px0 && py1 && pz1) atomicAdd(hb + base +  9, wx0 * wyz11);
        if (px1 && py0 && pz0) atomicAdd(hb + base + 64, wx1 * wyz00);
        if (px1 && py0 && pz1) atomicAdd(hb + base + 65, wx1 * wyz01);
        if (px1 && py1 && pz0) atomicAdd(hb + base + 72, wx1 * wyz10);
        if (px1 && py1 && pz1) atomicAdd(hb + base + 73, wx1 * wyz11);
    }

    // ---- last block per batch normalizes, writes out, resets scratch ----
    __threadfence();
    if (tid == 0) {
        const unsigned t = atomicAdd(&g_count[b], 1u);
        s_last = (t == gridDim.x - 1) ? 1 : 0;
    }
    __syncthreads();

    if (s_last) {
        __threadfence();
        const float v = (tid < KBINS) ? __ldcg(hb + tid) : 0.0f;

        float s = v;
        #pragma unroll
        for (int o = 16; o > 0; o >>= 1) s += __shfl_xor_sync(0xffffffffu, s, o);
        if ((tid & 31) == 0) red[tid >> 5] = s;
        __syncthreads();

        float total = 0.0f;
        #pragma unroll
        for (int k = 0; k < 32; ++k) total += red[k];

        if (tid < KBINS) {
            out[b * KBINS + tid] = v * __fdividef(1.0f, total + 1e-8f);
            // restore zero-invariant for the next graph replay
            hb[tid] = 0.0f;
        }
        if (tid == 0) g_count[b] = 0u;
    }
}

extern "C" void kernel_launch(void* const* d_in, const int* in_sizes, int n_in,
                              void* d_out, int out_size) {
    const float* x = (const float*)d_in[0];
    float* out = (float*)d_out;

    dim3 grid(GX, BATCH);
    dh_fused_kernel<<<grid, NTHR>>>(x, out);
}

// round 5
// speedup vs baseline: 5.6060x; 5.6060x over previous
#include <cuda_runtime.h>
#include <cuda_bf16.h>

#define BATCH 4
#define HW    65536           // 256*256 pixels per (batch,channel)
#define KBINS 512             // 8^3 bins
#define GX    74              // blocks/batch -> 296 CTAs = exactly 2/SM
#define NTHR  1024            // 2 CTAs/SM * 1024 = 2048 thr/SM = 100% occ
// -1 / (49 * 2*sigma^2), sigma = 0.02
#define NEG_COEF (-25.510204081632653f)
// tail truncation: far-bin relative weight at f=0.33 is exp(-25.51*0.34)=1.7e-4
#define TLO 0.33f
#define THI 0.67f

// Scratch (no cudaMalloc). Zero at module load; last block per batch resets
// it each run, preserving the invariant across graph replays.
__device__ float        g_hist[BATCH * KBINS];
__device__ unsigned int g_count[BATCH];

__global__ __launch_bounds__(NTHR, 2)
void dh_fused_kernel(const float* __restrict__ x, float* __restrict__ out) {
    __shared__ float sh[KBINS];     // block-private histogram (smem atomics)
    __shared__ float red[32];
    __shared__ int   s_last;

    const int b   = blockIdx.y;
    const int tid = threadIdx.x;

    if (tid < KBINS) sh[tid] = 0.0f;
    __syncthreads();

    // per-block contiguous scalar-pixel range: 885 or 886 per block (<=1024)
    const float* __restrict__ xb = x + (size_t)b * 3 * HW;
    const int start = (int)(((long long)blockIdx.x       * HW) / GX);
    const int end   = (int)(((long long)(blockIdx.x + 1) * HW) / GX);
    const int p     = start + tid;

    if (p < end) {
        const float tx = __ldg(xb + p)          * 7.0f;
        const float ty = __ldg(xb + HW + p)     * 7.0f;
        const float tz = __ldg(xb + 2 * HW + p) * 7.0f;
        const int ix = min((int)tx, 6);
        const int iy = min((int)ty, 6);
        const int iz = min((int)tz, 6);
        const float fx = tx - (float)ix;
        const float fy = ty - (float)iy;
        const float fz = tz - (float)iz;
        const float gx = 1.0f - fx, gy = 1.0f - fy, gz = 1.0f - fz;

        const float wx0 = __expf(NEG_COEF * fx * fx);
        const float wx1 = __expf(NEG_COEF * gx * gx);
        const float wy0 = __expf(NEG_COEF * fy * fy);
        const float wy1 = __expf(NEG_COEF * gy * gy);
        float       wz0 = __expf(NEG_COEF * fz * fz);
        float       wz1 = __expf(NEG_COEF * gz * gz);

        // exact per-pixel normalizer (all 6 weights; +1e-8 matters)
        const float S   = (wx0 + wx1) * (wy0 + wy1) * (wz0 + wz1);
        const float inv = __fdividef(1.0f, S + 1e-8f);
        wz0 *= inv;
        wz1 *= inv;

        const bool px0 = fx < THI, px1 = fx > TLO;
        const bool py0 = fy < THI, py1 = fy > TLO;
        const bool pz0 = fz < THI, pz1 = fz > TLO;

        const float wyz00 = wy0 * wz0, wyz01 = wy0 * wz1;
        const float wyz10 = wy1 * wz0, wyz11 = wy1 * wz1;
        const int base = ix * 64 + iy * 8 + iz;

        // shared-memory atomics: ~2 cyc/lane, aggregated per CTA before any
        // global traffic (global per-address contention killed R4)
        if (px0 && py0 && pz0) atomicAdd(&sh[base +  0], wx0 * wyz00);
        if (px0 && py0 && pz1) atomicAdd(&sh[base +  1], wx0 * wyz01);
        if (px0 && py1 && pz0) atomicAdd(&sh[base +  8], wx0 * wyz10);
        if (px0 && py1 && pz1) atomicAdd(&sh[base +  9], wx0 * wyz11);
        if (px1 && py0 && pz0) atomicAdd(&sh[base + 64], wx1 * wyz00);
        if (px1 && py0 && pz1) atomicAdd(&sh[base + 65], wx1 * wyz01);
        if (px1 && py1 && pz0) atomicAdd(&sh[base + 72], wx1 * wyz10);
        if (px1 && py1 && pz1) atomicAdd(&sh[base + 73], wx1 * wyz11);
    }

    __syncthreads();

    // flush block-private histogram: one bin per thread (tid < 512),
    // ~74 global adds per address total -> no L2 serialization issue
    if (tid < KBINS) {
        const float v = sh[tid];
        if (v != 0.0f) atomicAdd(&g_hist[b * KBINS + tid], v);
    }

    // ---- last block per batch normalizes, writes out, resets scratch ----
    __threadfence();
    if (tid == 0) {
        const unsigned t = atomicAdd(&g_count[b], 1u);
        s_last = (t == gridDim.x - 1) ? 1 : 0;
    }
    __syncthreads();

    if (s_last) {
        __threadfence();
        const float v = (tid < KBINS) ? __ldcg(&g_hist[b * KBINS + tid]) : 0.0f;

        float s = v;
        #pragma unroll
        for (int o = 16; o > 0; o >>= 1) s += __shfl_xor_sync(0xffffffffu, s, o);
        if ((tid & 31) == 0) red[tid >> 5] = s;
        __syncthreads();

        float total = 0.0f;
        #pragma unroll
        for (int k = 0; k < 32; ++k) total += red[k];

        if (tid < KBINS) {
            out[b * KBINS + tid] = v * __fdividef(1.0f, total + 1e-8f);
            // restore zero-invariant for the next graph replay
            g_hist[b * KBINS + tid] = 0.0f;
        }
        if (tid == 0) g_count[b] = 0u;
    }
}

extern "C" void kernel_launch(void* const* d_in, const int* in_sizes, int n_in,
                              void* d_out, int out_size) {
    const float* x = (const float*)d_in[0];
    float* out = (float*)d_out;

    dim3 grid(GX, BATCH);
    dh_fused_kernel<<<grid, NTHR>>>(x, out);
}